// round 10
// baseline (speedup 1.0000x reference)
#include <cuda_runtime.h>
#include <cstdint>

// YOLO-v2 loss, fused. BS=2048, H=W=14, A=5, NC=2, SIZE=7, G=30.
// One CTA per image; pred+label staged in SMEM; division-free noobj test;
// deterministic two-kernel reduction via __device__ global scratch.

#define TPB    256
#define Wd     14
#define Hd     14
#define Ad     5
#define SZd    7
#define HWd    196              // H*W
#define GMAXd  30
#define CELLSd 980              // HW*A
#define PREDN  (Ad*SZd*HWd)     // 6860 floats per image
#define LABN   (7*HWd)          // 1372 floats per image

__device__ float g_partial[4096];

__device__ __forceinline__ float fsigmoid(float x) {
    return __fdividef(1.0f, 1.0f + __expf(-x));
}

extern "C" __global__ void __launch_bounds__(TPB)
yolo_loss_main(const float* __restrict__ pred,
               const float* __restrict__ lab,
               const float* __restrict__ anchors,
               const int*   __restrict__ seen_p)
{
    __shared__ float sp[PREDN];             // pred[b] as [ch=a*7+s][hw]
    __shared__ float sl[LABN];              // label[b] as [ch][hw]
    __shared__ float gxl[GMAXd], gxr[GMAXd], gyt[GMAXd], gyb[GMAXd], gs6[GMAXd];
    __shared__ float gtco[GMAXd * 5];
    __shared__ int   gmid[GMAXd];           // cell*A + aid per ground truth
    __shared__ int   gflat[GMAXd];
    __shared__ int   wcnt[8], wbase[8];
    __shared__ int   s_cnt;
    __shared__ float s_aw[Ad], s_ah[Ad];
    __shared__ float s_red[8];

    const int b   = blockIdx.x;
    const int tid = threadIdx.x;

    // ---- Stage inputs into SMEM (vectorized, coalesced) ----
    {
        const float4* p4 = reinterpret_cast<const float4*>(pred + (size_t)b * PREDN);
        float4* s4 = reinterpret_cast<float4*>(sp);
        for (int i = tid; i < PREDN / 4; i += TPB) s4[i] = p4[i];
        const float4* l4 = reinterpret_cast<const float4*>(lab + (size_t)b * LABN);
        float4* sl4 = reinterpret_cast<float4*>(sl);
        for (int i = tid; i < LABN / 4; i += TPB) sl4[i] = l4[i];
    }
    if (tid < Ad) {
        // anchor_bias = anchors / (512/14) / [W,H]
        s_aw[tid] = anchors[2 * tid + 0] / (512.0f / 14.0f) / 14.0f;
        s_ah[tid] = anchors[2 * tid + 1] / (512.0f / 14.0f) / 14.0f;
    }
    __syncthreads();

    // ---- Ordered gather of ground-truth cells (obj > 0), ascending flat index.
    // top_k over {0,1} values with stable tie-break == first G positives by index.
    {
        bool f = (tid < HWd) && (sl[tid] > 0.0f);
        unsigned msk = __ballot_sync(0xffffffffu, f);
        int lane = tid & 31, w = tid >> 5;
        if (lane == 0) wcnt[w] = __popc(msk);
        __syncthreads();
        if (tid == 0) {
            int s = 0;
            for (int i = 0; i < 8; ++i) { wbase[i] = s; s += wcnt[i]; }
            s_cnt = (s < GMAXd) ? s : GMAXd;
        }
        __syncthreads();
        if (f) {
            int rank = wbase[w] + __popc(msk & ((1u << lane) - 1u));
            if (rank < GMAXd) gflat[rank] = tid;
        }
    }
    __syncthreads();

    float acc = 0.0f;
    const int cnt = s_cnt;

    // ---- Per-ground-truth precompute + selected-cell coord/obj/class terms ----
    if (tid < cnt) {
        int flat = gflat[tid];
        int r = flat / Wd, c = flat - r * Wd;
        float tx = sl[3 * HWd + flat], ty = sl[4 * HWd + flat];
        float tw = sl[5 * HWd + flat], th = sl[6 * HWd + flat];
        float gx = (tx + (float)c) / 14.0f;
        float gy = (ty + (float)r) / 14.0f;
        float twth = tw * th;

        // anchor argmax (strict > keeps first on ties, matching jnp.argmax)
        int aid = 0; float best = -1e30f;
        #pragma unroll
        for (int k = 0; k < Ad; ++k) {
            float ia = fminf(tw, s_aw[k]) * fminf(th, s_ah[k]);
            float sc = ia / (twth + s_aw[k] * s_ah[k] - ia);
            if (sc > best) { best = sc; aid = k; }
        }

        float gxW = gx * 14.0f, gyH = gy * 14.0f;
        int wi = (int)gxW, hj = (int)gyH;          // truncation; values positive
        float fx = gxW - (float)wi, fy = gyH - (float)hj;
        int cell = hj * Wd + wi;

        gxl[tid] = gx - 0.5f * tw;  gxr[tid] = gx + 0.5f * tw;
        gyt[tid] = gy - 0.5f * th;  gyb[tid] = gy + 0.5f * th;
        gs6[tid] = 0.6f * twth;
        gmid[tid] = cell * Ad + aid;

        float p0  = sp[(aid * SZd + 0) * HWd + cell];
        float p1  = sp[(aid * SZd + 1) * HWd + cell];
        float p2  = sp[(aid * SZd + 2) * HWd + cell];
        float p3  = sp[(aid * SZd + 3) * HWd + cell];
        float p4v = sp[(aid * SZd + 4) * HWd + cell];
        float p5  = sp[(aid * SZd + 5) * HWd + cell];
        float p6  = sp[(aid * SZd + 6) * HWd + cell];
        float sx = fsigmoid(p3), sy = fsigmoid(p4v);
        float lw = __logf(tw / s_aw[aid]);
        float lh = __logf(th / s_ah[aid]);
        float wgt = 2.0f - fx * fy;                 // COORD_SCALE = 1

        // iou_sel between predicted box at (hj,wi,aid) and this truth
        float x1 = (sx + (float)wi) / 14.0f;
        float y1 = (sy + (float)hj) / 14.0f;
        float w1 = __expf(p5) * s_aw[aid];
        float h1 = __expf(p6) * s_ah[aid];
        float ix = fminf(x1 + 0.5f * w1, gx + 0.5f * tw) - fmaxf(x1 - 0.5f * w1, gx - 0.5f * tw);
        float iy = fminf(y1 + 0.5f * h1, gy + 0.5f * th) - fmaxf(y1 - 0.5f * h1, gy - 0.5f * th);
        float inter = fmaxf(ix, 0.0f) * fmaxf(iy, 0.0f);
        float uni = w1 * h1 + twth - inter;
        float iou = fmaxf(inter / uni, 0.0f);

        gtco[tid * 5 + 0] = wgt * (sx - fx);
        gtco[tid * 5 + 1] = wgt * (sy - fy);
        gtco[tid * 5 + 2] = wgt * (p5 - lw);
        gtco[tid * 5 + 3] = wgt * (p6 - lh);
        gtco[tid * 5 + 4] = 5.0f * (p0 - iou);      // OBJ_SCALE = 5

        // class loss (CLASS_SCALE = 1), cvec from label channels 1,2 at (hj,wi)
        float l1 = sl[1 * HWd + cell], l2 = sl[2 * HWd + cell];
        acc += (p1 - l1) * (p1 - l1) + (p2 - l2) * (p2 - l2);
    }
    __syncthreads();

    // ---- 'seen' may arrive as int32 or float32 bits; 6400 decodes right either way
    int sv_raw = seen_p[0];
    long long sv = (sv_raw >= 0 && sv_raw < 100000000)
                   ? (long long)sv_raw
                   : (long long)__int_as_float(sv_raw);
    float pScale2 = (sv < 12800) ? 1e-4f : 0.0f;    // (0.01)^2 prior weight

    // ---- Per-cell pass: 4 cells per thread, all state in registers ----
    float xl[4], xr[4], yt[4], yb[4], ap6[4], pp0[4], prs[4];
    int   cA[4], hitg[4];
    bool  ok[4];
    #pragma unroll
    for (int j = 0; j < 4; ++j) {
        int idx = tid + j * TPB;
        bool act = idx < CELLSd;
        int ii = act ? idx : 0;
        int hw = ii / Ad, a = ii - hw * Ad;
        float p0  = sp[(a * SZd + 0) * HWd + hw];
        float p3  = sp[(a * SZd + 3) * HWd + hw];
        float p4v = sp[(a * SZd + 4) * HWd + hw];
        float p5  = sp[(a * SZd + 5) * HWd + hw];
        float p6  = sp[(a * SZd + 6) * HWd + hw];
        float sx = fsigmoid(p3), sy = fsigmoid(p4v);
        int wi = hw % Wd, hj = hw / Wd;
        float x1 = (sx + (float)wi) / 14.0f;
        float y1 = (sy + (float)hj) / 14.0f;
        float w1 = __expf(p5) * s_aw[a];
        float h1 = __expf(p6) * s_ah[a];
        xl[j] = x1 - 0.5f * w1;  xr[j] = x1 + 0.5f * w1;
        yt[j] = y1 - 0.5f * h1;  yb[j] = y1 + 0.5f * h1;
        ap6[j] = 0.6f * (w1 * h1);
        pp0[j] = p0;
        float dx = sx - 0.5f, dy = sy - 0.5f;
        prs[j] = pScale2 * (dx * dx + dy * dy + p5 * p5 + p6 * p6);
        cA[j] = act ? ii : -1;
        hitg[j] = -1;
        ok[j] = true;
    }

    // Hot loop: division-free "all IoU <= 0.6" test + gt-cell match.
    // inter <= 0.6*(Ap+At-inter)  <=>  1.6*inter <= 0.6*Ap + 0.6*At
    for (int g = 0; g < cnt; ++g) {
        float gl = gxl[g], gr = gxr[g], gtt = gyt[g], gb = gyb[g], gs = gs6[g];
        int gm = gmid[g];
        #pragma unroll
        for (int j = 0; j < 4; ++j) {
            float ix = fminf(xr[j], gr) - fmaxf(xl[j], gl);
            float iy = fminf(yb[j], gb) - fmaxf(yt[j], gtt);
            float inter = fmaxf(ix, 0.0f) * fmaxf(iy, 0.0f);
            ok[j] = ok[j] && (1.6f * inter <= ap6[j] + gs);
            if (cA[j] == gm) hitg[j] = g;
        }
    }

    // comb = m*ta + (1-m)*coord_obj  (gt cells are distinct -> m in {0,1})
    #pragma unroll
    for (int j = 0; j < 4; ++j) {
        if (cA[j] < 0) continue;
        if (hitg[j] >= 0) {
            int h5 = hitg[j] * 5;
            float t0 = gtco[h5 + 0], t1 = gtco[h5 + 1], t2 = gtco[h5 + 2];
            float t3 = gtco[h5 + 3], t4 = gtco[h5 + 4];
            acc += t0 * t0 + t1 * t1 + t2 * t2 + t3 * t3 + t4 * t4;
        } else {
            float no = ok[j] ? 0.5f * pp0[j] : 0.0f;   // NOOBJ_SCALE = 0.5
            acc += prs[j] + no * no;
        }
    }

    // ---- Block reduction ----
    #pragma unroll
    for (int o = 16; o > 0; o >>= 1) acc += __shfl_down_sync(0xffffffffu, acc, o);
    if ((tid & 31) == 0) s_red[tid >> 5] = acc;
    __syncthreads();
    if (tid < 8) {
        float v = s_red[tid];
        #pragma unroll
        for (int o = 4; o > 0; o >>= 1) v += __shfl_down_sync(0xffu, v, o);
        if (tid == 0) g_partial[b] = (cnt > 0) ? v : 0.0f;  // where(any(valid), il, 0)
    }
}

extern "C" __global__ void __launch_bounds__(TPB)
yolo_loss_reduce(float* __restrict__ out, int bs)
{
    __shared__ double sd[8];
    double s = 0.0;
    for (int i = threadIdx.x; i < bs; i += TPB) s += (double)g_partial[i];
    #pragma unroll
    for (int o = 16; o > 0; o >>= 1) s += __shfl_down_sync(0xffffffffu, s, o);
    if ((threadIdx.x & 31) == 0) sd[threadIdx.x >> 5] = s;
    __syncthreads();
    if (threadIdx.x < 8) {
        double v = sd[threadIdx.x];
        #pragma unroll
        for (int o = 4; o > 0; o >>= 1) v += __shfl_down_sync(0xffu, v, o);
        if (threadIdx.x == 0) out[0] = (float)(v / (double)bs);
    }
}

extern "C" void kernel_launch(void* const* d_in, const int* in_sizes, int n_in,
                              void* d_out, int out_size)
{
    const float* pred = (const float*)d_in[0];
    const float* lab  = (const float*)d_in[1];
    const float* anch = (const float*)d_in[2];
    const int*   seen = (const int*)d_in[3];
    int bs = in_sizes[0] / PREDN;
    if (bs > 4096) bs = 4096;
    yolo_loss_main<<<bs, TPB>>>(pred, lab, anch, seen);
    yolo_loss_reduce<<<1, TPB>>>((float*)d_out, bs);
}